// round 11
// baseline (speedup 1.0000x reference)
#include <cuda_runtime.h>
#include <cuda_fp16.h>
#include <cstdint>

// ---------------- problem constants ----------------
constexpr int B_ = 16, C_ = 64, H_ = 128, W_ = 128, O_ = 128, KE_ = 9;

// ---------------- device scratch ----------------
// w in MMA-fragment-major layout: [tap(9)][mblock(8)][ks(4)][lane(32)] -> uint4
__device__ __align__(16) uint4 g_wfrag[KE_ * 8 * 4 * 32];

// ---------------- smem layout (bytes): x tile only ----------------
// x tile: [3 padded rows][130 cols] rows of 128B (c=64 fp16), SW128
constexpr int XROWS = 3 * 130;                   // 390
constexpr int SMEM_TOTAL = XROWS * 128;          // 49920

__device__ __forceinline__ uint32_t sw(uint32_t off) { return off ^ ((off >> 3) & 0x70); }

__device__ __forceinline__ uint32_t smem_u32(const void* p) {
    uint32_t a;
    asm("{ .reg .u64 t; cvta.to.shared.u64 t, %1; cvt.u32.u64 %0, t; }" : "=r"(a) : "l"(p));
    return a;
}

__device__ __forceinline__ void ldsm4(uint32_t* r, uint32_t addr) {
    asm volatile("ldmatrix.sync.aligned.m8n8.x4.shared.b16 {%0,%1,%2,%3}, [%4];"
                 : "=r"(r[0]), "=r"(r[1]), "=r"(r[2]), "=r"(r[3]) : "r"(addr));
}

__device__ __forceinline__ void mma16816(float* d, const uint32_t* a, const uint32_t* b) {
    asm volatile(
        "mma.sync.aligned.m16n8k16.row.col.f32.f16.f16.f32 "
        "{%0,%1,%2,%3}, {%4,%5,%6,%7}, {%8,%9}, {%0,%1,%2,%3};"
        : "+f"(d[0]), "+f"(d[1]), "+f"(d[2]), "+f"(d[3])
        : "r"(a[0]), "r"(a[1]), "r"(a[2]), "r"(a[3]), "r"(b[0]), "r"(b[1]));
}

// ---------------- prep: w -> m16n8k16 A fragments (tiny) ------------------------
__global__ __launch_bounds__(256) void prep_w(const float* __restrict__ w) {
    int idx = blockIdx.x * 256 + threadIdx.x;   // KE*1024 = 9216 total
    if (idx < KE_ * 1024) {
        int l  = idx & 31;
        int ks = (idx >> 5) & 3;
        int mb = (idx >> 7) & 7;
        int k  = idx >> 10;
        int gid = l >> 2, tg2 = (l & 3) * 2;
        int o0 = mb * 16 + gid;
        int c0 = ks * 16 + tg2;
        auto wv = [&](int o, int c) { return __float2half(w[(o * C_ + c) * KE_ + k]); };
        __align__(16) __half h[8];
        h[0] = wv(o0, c0);         h[1] = wv(o0, c0 + 1);
        h[2] = wv(o0 + 8, c0);     h[3] = wv(o0 + 8, c0 + 1);
        h[4] = wv(o0, c0 + 8);     h[5] = wv(o0, c0 + 9);
        h[6] = wv(o0 + 8, c0 + 8); h[7] = wv(o0 + 8, c0 + 9);
        g_wfrag[idx] = *(const uint4*)h;
    }
}

// ---------------- main conv: row-pipelined staging + tensor mainloop ------------
__global__ __launch_bounds__(256, 2)
void conv_mma_kernel(const float* __restrict__ x, float* __restrict__ out) {
    extern __shared__ char smem[];
    const uint32_t sbase = smem_u32(smem);
    const int tid = threadIdx.x;
    const int l = tid & 31, wid = tid >> 5;
    const int warpM = (wid >> 1) * 32;   // o offset: 0,32,64,96
    const int warpN = (wid & 1) * 64;    // w offset: 0,64
    const int h0 = blockIdx.x, b = blockIdx.y;

    // per-lane ldmatrix pieces for B
    const int brow  = (l & 7) + ((l >> 4) & 1) * 8;
    const int bcolb = ((l >> 3) & 1) * 16;

    const size_t cstride = (size_t)H_ * W_;
    const float* xb = x + (size_t)b * C_ * cstride;

    // staging unit for this thread: chalf = c-half (0: c0..31, 1: c32..63), wp = col
    const int chalf = (tid >= 130) ? 1 : 0;
    const int wp = tid - 130 * chalf;          // wp < 130 for tid<260 (all 256 threads)
    const int gw = wp - 1;
    const bool wvalid = (unsigned)gw < (unsigned)W_;

    float st[32];                               // in-flight row data (raw fp32)

    // --- issue LDGs for padded row r into st ---
    auto issue_row = [&](int r) {
        int gh = h0 - 1 + r;
        bool valid = wvalid && ((unsigned)gh < (unsigned)H_);
        const float* src = xb + ((size_t)chalf * 32) * cstride + (size_t)gh * W_ + gw;
        #pragma unroll
        for (int j = 0; j < 32; j++)
            st[j] = valid ? __ldg(src + j * cstride) : 0.0f;
    };
    // --- convert + store st into smem row r; also handle 4 leftover units ---
    auto commit_row = [&](int r) {
        int row = r * 130 + wp;
        #pragma unroll
        for (int q = 0; q < 4; q++) {
            __half2 p0 = __floats2half2_rn(st[8 * q + 0], st[8 * q + 1]);
            __half2 p1 = __floats2half2_rn(st[8 * q + 2], st[8 * q + 3]);
            __half2 p2 = __floats2half2_rn(st[8 * q + 4], st[8 * q + 5]);
            __half2 p3 = __floats2half2_rn(st[8 * q + 6], st[8 * q + 7]);
            uint4 v = make_uint4(*(uint32_t*)&p0, *(uint32_t*)&p1,
                                 *(uint32_t*)&p2, *(uint32_t*)&p3);
            *(uint4*)(smem + sw(row * 128 + (chalf * 4 + q) * 16)) = v;
        }
        if (tid < 4) {                           // leftover units u=256..259
            int wp2 = 126 + tid;
            int gw2 = wp2 - 1;
            int gh = h0 - 1 + r;
            bool valid = ((unsigned)gw2 < (unsigned)W_) && ((unsigned)gh < (unsigned)H_);
            const float* src = xb + (size_t)32 * cstride + (size_t)gh * W_ + gw2;
            int row2 = r * 130 + wp2;
            #pragma unroll
            for (int q = 0; q < 4; q++) {
                float f0 = valid ? __ldg(src + (8 * q + 0) * cstride) : 0.0f;
                float f1 = valid ? __ldg(src + (8 * q + 1) * cstride) : 0.0f;
                float f2 = valid ? __ldg(src + (8 * q + 2) * cstride) : 0.0f;
                float f3 = valid ? __ldg(src + (8 * q + 3) * cstride) : 0.0f;
                float f4 = valid ? __ldg(src + (8 * q + 4) * cstride) : 0.0f;
                float f5 = valid ? __ldg(src + (8 * q + 5) * cstride) : 0.0f;
                float f6 = valid ? __ldg(src + (8 * q + 6) * cstride) : 0.0f;
                float f7 = valid ? __ldg(src + (8 * q + 7) * cstride) : 0.0f;
                __half2 p0 = __floats2half2_rn(f0, f1), p1 = __floats2half2_rn(f2, f3);
                __half2 p2 = __floats2half2_rn(f4, f5), p3 = __floats2half2_rn(f6, f7);
                uint4 v = make_uint4(*(uint32_t*)&p0, *(uint32_t*)&p1,
                                     *(uint32_t*)&p2, *(uint32_t*)&p3);
                *(uint4*)(smem + sw(row2 * 128 + (4 + q) * 16)) = v;
            }
        }
    };

    float acc[2][8][4];
    #pragma unroll
    for (int mt = 0; mt < 2; mt++)
        #pragma unroll
        for (int nt = 0; nt < 8; nt++)
            #pragma unroll
            for (int q = 0; q < 4; q++) acc[mt][nt][q] = 0.0f;

    // base index into g_wfrag for this warp: [t][mb = warpM/16 + mt][ks][l]
    const uint4* wf = g_wfrag + (warpM >> 4) * 128 + l;

    // ---- pipelined staging + compute ----
    issue_row(0);
    commit_row(0);
    issue_row(1);                 // row-1 LDGs fly during MMA(dh=0)
    __syncthreads();

    #pragma unroll
    for (int dh = 0; dh < 3; dh++) {
        #pragma unroll
        for (int dw = 0; dw < 3; dw++) {
            const int t = dh * 3 + dw;
            const int browbase = dh * 130 + warpN + brow + dw;
            const uint4* wft = wf + t * 1024;

            #pragma unroll
            for (int ks = 0; ks < 4; ks++) {
                uint4 af[2];
                #pragma unroll
                for (int mt = 0; mt < 2; mt++)
                    af[mt] = wft[mt * 128 + ks * 32];    // LDG.128, L1/L2-resident
                #pragma unroll
                for (int np = 0; np < 4; np++) {         // np-inner: bb live = 4 regs
                    uint32_t bb[4];
                    uint32_t rn = (uint32_t)(browbase + np * 16);
                    ldsm4(bb, sbase + sw(rn * 128 + ks * 32 + bcolb));
                    #pragma unroll
                    for (int mt = 0; mt < 2; mt++) {
                        mma16816(acc[mt][2 * np],     (const uint32_t*)&af[mt], &bb[0]);
                        mma16816(acc[mt][2 * np + 1], (const uint32_t*)&af[mt], &bb[2]);
                    }
                }
            }
        }
        if (dh < 2) {
            commit_row(dh + 1);
            if (dh == 0) issue_row(2);   // row-2 LDGs fly during MMA(dh=1)
            __syncthreads();
        }
    }

    // ---- epilogue: fragment -> out[b][o][h0][w], float2 stores ----
    const int gid = l >> 2, tg = l & 3;
    #pragma unroll
    for (int mt = 0; mt < 2; mt++)
        #pragma unroll
        for (int half = 0; half < 2; half++) {
            int o = warpM + mt * 16 + gid + half * 8;
            float* dst = out + (((size_t)b * O_ + o) * H_ + h0) * W_ + warpN + 2 * tg;
            #pragma unroll
            for (int nt = 0; nt < 8; nt++) {
                float2 v = make_float2(acc[mt][nt][half * 2], acc[mt][nt][half * 2 + 1]);
                *(float2*)(dst + nt * 8) = v;
            }
        }
}

// ---------------- launch ----------------
extern "C" void kernel_launch(void* const* d_in, const int* in_sizes, int n_in,
                              void* d_out, int out_size) {
    const float* x = (const float*)d_in[0];
    const float* w = (const float*)d_in[1];
    float* out = (float*)d_out;

    cudaFuncSetAttribute(conv_mma_kernel, cudaFuncAttributeMaxDynamicSharedMemorySize,
                         SMEM_TOTAL);

    prep_w<<<36, 256>>>(w);
    conv_mma_kernel<<<dim3(H_, B_), 256, SMEM_TOTAL>>>(x, out);
}